// round 3
// baseline (speedup 1.0000x reference)
#include <cuda_runtime.h>

// Elementwise affine: y = x * 2 + 5 over 8192*8192 fp32.
// HBM streamer, ILP=4: four independent 128-bit streaming loads issued
// front-to-back per thread (MLP_p1=4), then four streaming stores.
// 16777216 float4 total; 256 thr/block * 4 float4/thr -> 16384 blocks.

__global__ void __launch_bounds__(256) affine_kernel(const float4* __restrict__ x,
                                                     float4* __restrict__ y) {
    unsigned int base = blockIdx.x * 1024u + threadIdx.x;

    float4 v0 = __ldcs(&x[base]);
    float4 v1 = __ldcs(&x[base + 256u]);
    float4 v2 = __ldcs(&x[base + 512u]);
    float4 v3 = __ldcs(&x[base + 768u]);

    float4 r0, r1, r2, r3;
    r0.x = fmaf(v0.x, 2.0f, 5.0f); r0.y = fmaf(v0.y, 2.0f, 5.0f);
    r0.z = fmaf(v0.z, 2.0f, 5.0f); r0.w = fmaf(v0.w, 2.0f, 5.0f);
    r1.x = fmaf(v1.x, 2.0f, 5.0f); r1.y = fmaf(v1.y, 2.0f, 5.0f);
    r1.z = fmaf(v1.z, 2.0f, 5.0f); r1.w = fmaf(v1.w, 2.0f, 5.0f);
    r2.x = fmaf(v2.x, 2.0f, 5.0f); r2.y = fmaf(v2.y, 2.0f, 5.0f);
    r2.z = fmaf(v2.z, 2.0f, 5.0f); r2.w = fmaf(v2.w, 2.0f, 5.0f);
    r3.x = fmaf(v3.x, 2.0f, 5.0f); r3.y = fmaf(v3.y, 2.0f, 5.0f);
    r3.z = fmaf(v3.z, 2.0f, 5.0f); r3.w = fmaf(v3.w, 2.0f, 5.0f);

    __stcs(&y[base],         r0);
    __stcs(&y[base + 256u],  r1);
    __stcs(&y[base + 512u],  r2);
    __stcs(&y[base + 768u],  r3);
}

extern "C" void kernel_launch(void* const* d_in, const int* in_sizes, int n_in,
                              void* d_out, int out_size) {
    const float4* x = (const float4*)d_in[0];
    float4* y = (float4*)d_out;
    int n = in_sizes[0];            // 67108864
    int n4 = n / 4;                 // 16777216
    int blocks = n4 / 1024;         // 16384
    affine_kernel<<<blocks, 256>>>(x, y);
}

// round 4
// speedup vs baseline: 1.0020x; 1.0020x over previous
#include <cuda_runtime.h>

// Elementwise affine: y = x * 2 + 5 over 8192*8192 fp32.
// HBM streamer, ILP=8: eight independent 128-bit streaming loads issued
// front-to-back per thread (32 outstanding 128B lines per warp), then
// eight streaming stores.
// 16777216 float4 total; 256 thr/block * 8 float4/thr -> 8192 blocks.

__global__ void __launch_bounds__(256) affine_kernel(const float4* __restrict__ x,
                                                     float4* __restrict__ y) {
    unsigned int base = blockIdx.x * 2048u + threadIdx.x;

    float4 v[8];
#pragma unroll
    for (int k = 0; k < 8; k++)
        v[k] = __ldcs(&x[base + k * 256u]);

#pragma unroll
    for (int k = 0; k < 8; k++) {
        float4 r;
        r.x = fmaf(v[k].x, 2.0f, 5.0f);
        r.y = fmaf(v[k].y, 2.0f, 5.0f);
        r.z = fmaf(v[k].z, 2.0f, 5.0f);
        r.w = fmaf(v[k].w, 2.0f, 5.0f);
        __stcs(&y[base + k * 256u], r);
    }
}

extern "C" void kernel_launch(void* const* d_in, const int* in_sizes, int n_in,
                              void* d_out, int out_size) {
    const float4* x = (const float4*)d_in[0];
    float4* y = (float4*)d_out;
    int n = in_sizes[0];            // 67108864
    int n4 = n / 4;                 // 16777216
    int blocks = n4 / 2048;         // 8192
    affine_kernel<<<blocks, 256>>>(x, y);
}